// round 15
// baseline (speedup 1.0000x reference)
#include <cuda_runtime.h>
#include <cuda_bf16.h>
#include <cstdint>

// Problem constants
#define N_NODES 100000
#define NPAD    100096          // multiple of 128
#define E_EDGES 1600000
#define F_INDIM 64
#define H       128
#define OUT_DIM 8
#define R_REL   10
#define B_BASES 4
#define L_LAYERS 3
#define KTOT    640             // 4*128 (bases) + 128 (root)
#define NSCANBLK 98             // ceil(NPAD/1024)

// ---------------- scratch (static __device__, zero-initialized at load) ----
__device__ float g_h[(size_t)NPAD * H];
__device__ float g_C[(size_t)B_BASES * NPAD * H];    // [b][n][H]
__device__ int   g_cnt[NPAD * R_REL];
__device__ float g_inv[NPAD * R_REL];
__device__ int   g_rowptr[NPAD + 1];
__device__ int   g_cursor[NPAD];
__device__ int   g_adj[E_EDGES];                     // src | (rtype<<20)
__device__ int   g_bs[NSCANBLK];
// transposed bf16 hi/lo weights: [l][n_out=128][k=640]
__device__ __nv_bfloat16 g_Whi[(size_t)L_LAYERS * 128 * KTOT];
__device__ __nv_bfloat16 g_Wlo[(size_t)L_LAYERS * 128 * KTOT];

__device__ __forceinline__ uint32_t pack_bf16(float a, float b) {
    __nv_bfloat162 t = __floats2bfloat162_rn(a, b);
    return *(uint32_t*)&t;
}

#define MMA16816(d, a, b) \
    asm volatile("mma.sync.aligned.m16n8k16.row.col.f32.bf16.bf16.f32 " \
        "{%0,%1,%2,%3}, {%4,%5,%6,%7}, {%8,%9}, {%0,%1,%2,%3};" \
        : "+f"((d)[0]), "+f"((d)[1]), "+f"((d)[2]), "+f"((d)[3]) \
        : "r"((a)[0]), "r"((a)[1]), "r"((a)[2]), "r"((a)[3]), \
          "r"((b)[0]), "r"((b)[1]))

#define LDSM4(r0, r1, r2, r3, addr) \
    asm volatile("ldmatrix.sync.aligned.m8n8.x4.shared.b16 {%0,%1,%2,%3}, [%4];" \
        : "=r"(r0), "=r"(r1), "=r"(r2), "=r"(r3) : "r"(addr))

// ---------------- input projection: h = x @ in_w + in_b  (K=64) ------------
__global__ void k_proj(const float* __restrict__ x, const float* __restrict__ w,
                       const float* __restrict__ b) {
    __shared__ float sm[12288];
    float* Ws = sm;              // [64][128]
    float* Xt = sm + 64 * 128;   // [k=64][node=64]
    int tid = threadIdx.x;
    int n0  = blockIdx.x * 64;

    float4* Ws4 = (float4*)Ws;
    const float4* w4 = (const float4*)w;
#pragma unroll
    for (int i = 0; i < 8; i++) Ws4[i * 256 + tid] = w4[i * 256 + tid];

#pragma unroll
    for (int i = 0; i < 4; i++) {
        int q = i * 256 + tid;
        int node = q & 63;
        int kq   = q >> 6;
        float4 v = make_float4(0.f, 0.f, 0.f, 0.f);
        int n = n0 + node;
        if (n < N_NODES) v = ((const float4*)x)[(size_t)n * 16 + kq];
        Xt[(kq * 4 + 0) * 64 + node] = v.x;
        Xt[(kq * 4 + 1) * 64 + node] = v.y;
        Xt[(kq * 4 + 2) * 64 + node] = v.z;
        Xt[(kq * 4 + 3) * 64 + node] = v.w;
    }
    __syncthreads();

    int ty = tid >> 4, tx = tid & 15;
    float acc[4][8] = {};
    const float4* Xt4 = (const float4*)Xt;
#pragma unroll 8
    for (int k = 0; k < 64; k++) {
        float4 xa = Xt4[k * 16 + ty];
        float4 wa = Ws4[k * 32 + tx];
        float4 wb = Ws4[k * 32 + 16 + tx];
        float xv[4] = {xa.x, xa.y, xa.z, xa.w};
        float wv[8] = {wa.x, wa.y, wa.z, wa.w, wb.x, wb.y, wb.z, wb.w};
#pragma unroll
        for (int i = 0; i < 4; i++)
#pragma unroll
            for (int j = 0; j < 8; j++) acc[i][j] += xv[i] * wv[j];
    }

    float4 ba = ((const float4*)b)[tx];
    float4 bb = ((const float4*)b)[16 + tx];
#pragma unroll
    for (int i = 0; i < 4; i++) {
        int n = n0 + ty * 4 + i;
        float4 o1 = make_float4(acc[i][0] + ba.x, acc[i][1] + ba.y,
                                acc[i][2] + ba.z, acc[i][3] + ba.w);
        float4 o2 = make_float4(acc[i][4] + bb.x, acc[i][5] + bb.y,
                                acc[i][6] + bb.z, acc[i][7] + bb.w);
        ((float4*)g_h)[(size_t)n * 32 + tx]      = o1;
        ((float4*)g_h)[(size_t)n * 32 + 16 + tx] = o2;
    }
}

// ---------------- weight prep: transpose + bf16 hi/lo split (once/call) ----
__global__ void k_prep(const float* __restrict__ bases, const float* __restrict__ root) {
    int i = blockIdx.x * 256 + threadIdx.x;
    if (i >= L_LAYERS * KTOT * 128) return;
    int n = i & 127;
    int k = (i >> 7) % KTOT;
    int l = i / (KTOT * 128);
    float w;
    if (k < 512)
        w = bases[((((size_t)l * B_BASES + (k >> 7)) * H) + (k & 127)) * H + n];
    else
        w = root[((size_t)l * H + (k - 512)) * H + n];
    __nv_bfloat16 hi = __float2bfloat16(w);
    __nv_bfloat16 lo = __float2bfloat16(w - __bfloat162float(hi));
    size_t idx = ((size_t)l * 128 + n) * KTOT + k;
    g_Whi[idx] = hi;
    g_Wlo[idx] = lo;
}

// ---------------- CSR build ------------------------------------------------
__global__ void k_zero_cnt() {
    int i = blockIdx.x * 256 + threadIdx.x;
    if (i < NPAD * R_REL) g_cnt[i] = 0;
}

__global__ void k_count(const int* __restrict__ ei, const int* __restrict__ et) {
    int e = blockIdx.x * 256 + threadIdx.x;
    if (e < E_EDGES) {
        int d = ei[E_EDGES + e];
        int r = et[e];
        atomicAdd(&g_cnt[d * R_REL + r], 1);
    }
}

// scan stage A: per-1024-chunk exclusive scan of degrees (deg = sum_r cnt).
// Also writes g_inv inline (folded former k_inv kernel).
__global__ void k_scanA() {
    __shared__ int sm[256];
    int t = threadIdx.x;
    int base = blockIdx.x * 1024 + t * 4;
    int d[4];
#pragma unroll
    for (int j = 0; j < 4; j++) {
        int idx = base + j;
        int s = 0;
        if (idx < NPAD) {
#pragma unroll
            for (int r = 0; r < R_REL; r++) {
                int c = g_cnt[idx * R_REL + r];
                s += c;
                g_inv[idx * R_REL + r] = 1.0f / (float)(c > 1 ? c : 1);
            }
        }
        d[j] = s;
    }
    int tot = d[0] + d[1] + d[2] + d[3];
    sm[t] = tot;
    __syncthreads();
    int run = tot;
    for (int o = 1; o < 256; o <<= 1) {
        int v = (t >= o) ? sm[t - o] : 0;
        __syncthreads();
        sm[t] += v;
        __syncthreads();
    }
    int excl = sm[t] - run;
    if (t == 255) g_bs[blockIdx.x] = sm[255];
    int acc = excl;
#pragma unroll
    for (int j = 0; j < 4; j++) {
        int idx = base + j;
        if (idx < NPAD) g_rowptr[idx] = acc;
        acc += d[j];
    }
}

// scan stage B: exclusive scan of the 98 block sums (single block)
__global__ void k_scanB() {
    __shared__ int sm[128];
    int t = threadIdx.x;
    int v = (t < NSCANBLK) ? g_bs[t] : 0;
    sm[t] = v;
    __syncthreads();
    for (int o = 1; o < 128; o <<= 1) {
        int u = (t >= o) ? sm[t - o] : 0;
        __syncthreads();
        sm[t] += u;
        __syncthreads();
    }
    if (t < NSCANBLK) g_bs[t] = sm[t] - v;
}

// scan stage C: add block offsets, init cursor, set sentinel
__global__ void k_scanC() {
    int i = blockIdx.x * 256 + threadIdx.x;
    if (i < NPAD) {
        int v = g_rowptr[i] + g_bs[i >> 10];
        g_rowptr[i] = v;
        g_cursor[i] = v;
    }
    if (i == 0) g_rowptr[NPAD] = E_EDGES;
}

__global__ void k_fill(const int* __restrict__ ei, const int* __restrict__ et) {
    int e = blockIdx.x * 256 + threadIdx.x;
    if (e < E_EDGES) {
        int s = ei[e];
        int d = ei[E_EDGES + e];
        int r = et[e];
        int pos = atomicAdd(&g_cursor[d], 1);
        g_adj[pos] = s | (r << 20);
    }
}

// ---------------- gather-aggregate: C[b][n][:] = sum_e comp[r,b]/cnt * h[src]
// one warp per dst node; 8-edge unroll for load MLP; h gathers hit L2.
__global__ void __launch_bounds__(256) k_gather(const float* __restrict__ comp_l) {
    __shared__ float scomp[R_REL * B_BASES];
    if (threadIdx.x < R_REL * B_BASES) scomp[threadIdx.x] = comp_l[threadIdx.x];
    __syncthreads();
    int wid = threadIdx.x >> 5, lane = threadIdx.x & 31;
    int n = blockIdx.x * 8 + wid;
    if (n >= NPAD) return;
    int beg = g_rowptr[n], end = g_rowptr[n + 1];

    float myinv = (lane < R_REL && n < N_NODES) ? g_inv[n * R_REL + lane] : 0.f;

    const float4* h4 = (const float4*)g_h;
    float4 c[B_BASES];
#pragma unroll
    for (int b = 0; b < B_BASES; b++) c[b] = make_float4(0.f, 0.f, 0.f, 0.f);

    int e = beg;
    for (; e + 7 < end; e += 8) {
        int    p[8];
        int    sidx[8], ridx[8];
        float4 v[8];
        float  iw[8];
#pragma unroll
        for (int j = 0; j < 8; j++) p[j] = g_adj[e + j];
#pragma unroll
        for (int j = 0; j < 8; j++) { sidx[j] = p[j] & 0xFFFFF; ridx[j] = p[j] >> 20; }
#pragma unroll
        for (int j = 0; j < 8; j++) v[j] = h4[(size_t)sidx[j] * 32 + lane];
#pragma unroll
        for (int j = 0; j < 8; j++) iw[j] = __shfl_sync(0xFFFFFFFFu, myinv, ridx[j]);
#pragma unroll
        for (int b = 0; b < B_BASES; b++) {
#pragma unroll
            for (int j = 0; j < 8; j++) {
                float w = scomp[ridx[j] * B_BASES + b] * iw[j];
                c[b].x += w * v[j].x;
                c[b].y += w * v[j].y;
                c[b].z += w * v[j].z;
                c[b].w += w * v[j].w;
            }
        }
    }
    for (; e + 3 < end; e += 4) {
        int p0 = g_adj[e], p1 = g_adj[e + 1], p2 = g_adj[e + 2], p3 = g_adj[e + 3];
        int s0 = p0 & 0xFFFFF, r0 = p0 >> 20;
        int s1 = p1 & 0xFFFFF, r1 = p1 >> 20;
        int s2 = p2 & 0xFFFFF, r2 = p2 >> 20;
        int s3 = p3 & 0xFFFFF, r3 = p3 >> 20;
        float4 v0 = h4[(size_t)s0 * 32 + lane];
        float4 v1 = h4[(size_t)s1 * 32 + lane];
        float4 v2 = h4[(size_t)s2 * 32 + lane];
        float4 v3 = h4[(size_t)s3 * 32 + lane];
        float i0 = __shfl_sync(0xFFFFFFFFu, myinv, r0);
        float i1 = __shfl_sync(0xFFFFFFFFu, myinv, r1);
        float i2 = __shfl_sync(0xFFFFFFFFu, myinv, r2);
        float i3 = __shfl_sync(0xFFFFFFFFu, myinv, r3);
#pragma unroll
        for (int b = 0; b < B_BASES; b++) {
            float w0 = scomp[r0 * B_BASES + b] * i0;
            float w1 = scomp[r1 * B_BASES + b] * i1;
            float w2 = scomp[r2 * B_BASES + b] * i2;
            float w3 = scomp[r3 * B_BASES + b] * i3;
            c[b].x += w0 * v0.x + w1 * v1.x + w2 * v2.x + w3 * v3.x;
            c[b].y += w0 * v0.y + w1 * v1.y + w2 * v2.y + w3 * v3.y;
            c[b].z += w0 * v0.z + w1 * v1.z + w2 * v2.z + w3 * v3.z;
            c[b].w += w0 * v0.w + w1 * v1.w + w2 * v2.w + w3 * v3.w;
        }
    }
    for (; e < end; e++) {
        int p0 = g_adj[e];
        int s0 = p0 & 0xFFFFF, r0 = p0 >> 20;
        float4 v0 = h4[(size_t)s0 * 32 + lane];
        float i0 = __shfl_sync(0xFFFFFFFFu, myinv, r0);
#pragma unroll
        for (int b = 0; b < B_BASES; b++) {
            float w0 = scomp[r0 * B_BASES + b] * i0;
            c[b].x += w0 * v0.x;
            c[b].y += w0 * v0.y;
            c[b].z += w0 * v0.z;
            c[b].w += w0 * v0.w;
        }
    }

    float4* C4 = (float4*)g_C;
#pragma unroll
    for (int b = 0; b < B_BASES; b++)
        C4[((size_t)b * NPAD + n) * 32 + lane] = c[b];
}

// ---------------- fused conv GEMM + bias + LayerNorm + ReLU + residual -----
// Per CTA: D[128 nodes, 128 out] = X[128, 640] @ W^T, X = [C0..C3, h] fp32,
// then h_new = (l>0 ? h_old : 0) + relu(LN(D + conv_b)), written to g_h.
// Mainloop is software-pipelined: chunk kc+1's global loads (X fp32 + W bf16)
// are prefetched into registers before chunk kc's MMA section.
__global__ void __launch_bounds__(256, 2)
k_conv_fused(int l, const float* __restrict__ cb,
             const float* __restrict__ lng, const float* __restrict__ lnb,
             int addres) {
    __shared__ __nv_bfloat16 sXhi[128][40];
    __shared__ __nv_bfloat16 sXlo[128][40];
    __shared__ __nv_bfloat16 sWhi[128][40];
    __shared__ __nv_bfloat16 sWlo[128][40];
    __shared__ float s_sum[128], s_sq[128];
    __shared__ float s_g[128], s_b[128], s_cb[128];

    int tid  = threadIdx.x;
    int warp = tid >> 5, lane = tid & 31;
    int g = lane >> 2, tig = lane & 3;
    int n0   = blockIdx.x * 128;
    int mrow = (warp >> 1) * 32;
    int ncol = (warp & 1) * 64;

    if (tid < 128) {
        s_sum[tid] = 0.f;
        s_sq[tid]  = 0.f;
        s_g[tid]   = lng[tid];
        s_b[tid]   = lnb[tid];
        s_cb[tid]  = cb[tid];
    }

    uint32_t sXhi_b = (uint32_t)__cvta_generic_to_shared(&sXhi[0][0]);
    uint32_t sXlo_b = (uint32_t)__cvta_generic_to_shared(&sXlo[0][0]);
    uint32_t sWhi_b = (uint32_t)__cvta_generic_to_shared(&sWhi[0][0]);
    uint32_t sWlo_b = (uint32_t)__cvta_generic_to_shared(&sWlo[0][0]);

    // ldmatrix per-lane byte offsets (within the [128][40] bf16 arrays)
    uint32_t a_off = (uint32_t)(((mrow + ((lane >> 3) & 1) * 8 + (lane & 7)) * 40
                                 + (lane >> 4) * 8) * 2);
    uint32_t b_off = (uint32_t)(((ncol + ((lane >> 4) & 1) * 8 + (lane & 7)) * 40
                                 + ((lane >> 3) & 1) * 8) * 2);

    float acc[2][8][4];
#pragma unroll
    for (int mt = 0; mt < 2; mt++)
#pragma unroll
        for (int nt = 0; nt < 8; nt++)
#pragma unroll
            for (int q = 0; q < 4; q++) acc[mt][nt][q] = 0.f;

    const __nv_bfloat16* whi = g_Whi + (size_t)l * 128 * KTOT;
    const __nv_bfloat16* wlo = g_Wlo + (size_t)l * 128 * KTOT;

    int row = tid >> 1, half = tid & 1;

    // prefetch chunk 0
    float4 px[4];
    uint4  pwh[2], pwl[2];
    {
        const float4* xs4 = (const float4*)(g_C + ((size_t)0 * NPAD + (n0 + row)) * H
                                            + half * 16);
#pragma unroll
        for (int j = 0; j < 4; j++) px[j] = xs4[j];
        const uint4* wh4 = (const uint4*)(whi + (size_t)row * KTOT + half * 16);
        const uint4* wl4 = (const uint4*)(wlo + (size_t)row * KTOT + half * 16);
        pwh[0] = wh4[0]; pwh[1] = wh4[1];
        pwl[0] = wl4[0]; pwl[1] = wl4[1];
    }

    for (int kc = 0; kc < 20; kc++) {
        __syncthreads();   // previous chunk's MMA reads complete
        // store prefetched X (with bf16 hi/lo split) and W to smem
#pragma unroll
        for (int j = 0; j < 4; j++) {
            float4 v = px[j];
            float hx = __bfloat162float(__float2bfloat16(v.x));
            float hy = __bfloat162float(__float2bfloat16(v.y));
            float hz = __bfloat162float(__float2bfloat16(v.z));
            float hw = __bfloat162float(__float2bfloat16(v.w));
            int col = half * 16 + j * 4;
            *(uint2*)&sXhi[row][col] = make_uint2(pack_bf16(v.x, v.y), pack_bf16(v.z, v.w));
            *(uint2*)&sXlo[row][col] = make_uint2(pack_bf16(v.x - hx, v.y - hy),
                                                  pack_bf16(v.z - hz, v.w - hw));
        }
        *(uint4*)&sWhi[row][half * 16]     = pwh[0];
        *(uint4*)&sWhi[row][half * 16 + 8] = pwh[1];
        *(uint4*)&sWlo[row][half * 16]     = pwl[0];
        *(uint4*)&sWlo[row][half * 16 + 8] = pwl[1];
        __syncthreads();

        // prefetch chunk kc+1 (overlaps the MMA section below)
        if (kc < 19) {
            int kn = kc + 1;
            int c = kn >> 2, koff = (kn & 3) * 32;
            const float* xs = (c < 4)
                ? g_C + ((size_t)c * NPAD + (n0 + row)) * H + koff + half * 16
                : g_h + (size_t)(n0 + row) * H + koff + half * 16;
            const float4* xs4 = (const float4*)xs;
#pragma unroll
            for (int j = 0; j < 4; j++) px[j] = xs4[j];
            const uint4* wh4 = (const uint4*)(whi + (size_t)row * KTOT + kn * 32 + half * 16);
            const uint4* wl4 = (const uint4*)(wlo + (size_t)row * KTOT + kn * 32 + half * 16);
            pwh[0] = wh4[0]; pwh[1] = wh4[1];
            pwl[0] = wl4[0]; pwl[1] = wl4[1];
        }

#pragma unroll
        for (int ks = 0; ks < 32; ks += 16) {
            uint32_t ah[2][4], al[2][4], bb[8][2];
            uint32_t ksb = (uint32_t)(ks * 2);
#pragma unroll
            for (int mt = 0; mt < 2; mt++) {
                uint32_t mo = (uint32_t)(mt * 16 * 40 * 2) + ksb;
                LDSM4(ah[mt][0], ah[mt][1], ah[mt][2], ah[mt][3], sXhi_b + a_off + mo);
                LDSM4(al[mt][0], al[mt][1], al[mt][2], al[mt][3], sXlo_b + a_off + mo);
            }
#pragma unroll
            for (int np = 0; np < 4; np++) {
                uint32_t no = (uint32_t)(np * 16 * 40 * 2) + ksb;
                LDSM4(bb[2 * np][0], bb[2 * np][1], bb[2 * np + 1][0], bb[2 * np + 1][1],
                      sWhi_b + b_off + no);
            }
#pragma unroll
            for (int mt = 0; mt < 2; mt++)
#pragma unroll
                for (int nt = 0; nt < 8; nt++) {
                    MMA16816(acc[mt][nt], ah[mt], bb[nt]);   // hi*hi
                    MMA16816(acc[mt][nt], al[mt], bb[nt]);   // lo*hi
                }
#pragma unroll
            for (int np = 0; np < 4; np++) {
                uint32_t no = (uint32_t)(np * 16 * 40 * 2) + ksb;
                LDSM4(bb[2 * np][0], bb[2 * np][1], bb[2 * np + 1][0], bb[2 * np + 1][1],
                      sWlo_b + b_off + no);
            }
#pragma unroll
            for (int mt = 0; mt < 2; mt++)
#pragma unroll
                for (int nt = 0; nt < 8; nt++)
                    MMA16816(acc[mt][nt], ah[mt], bb[nt]);   // hi*lo
        }
    }

    // ---- fused epilogue: bias -> LN stats -> LN+ReLU+residual -> g_h ----
#pragma unroll
    for (int mt = 0; mt < 2; mt++) {
        float s0 = 0.f, q0 = 0.f, s1 = 0.f, q1 = 0.f;
#pragma unroll
        for (int nt = 0; nt < 8; nt++) {
            int colg = ncol + nt * 8 + tig * 2;
            float bx = s_cb[colg], by = s_cb[colg + 1];
            float a0 = acc[mt][nt][0] + bx, a1 = acc[mt][nt][1] + by;
            float a2 = acc[mt][nt][2] + bx, a3 = acc[mt][nt][3] + by;
            acc[mt][nt][0] = a0; acc[mt][nt][1] = a1;
            acc[mt][nt][2] = a2; acc[mt][nt][3] = a3;
            s0 += a0 + a1; q0 += a0 * a0 + a1 * a1;
            s1 += a2 + a3; q1 += a2 * a2 + a3 * a3;
        }
#pragma unroll
        for (int o = 1; o <= 2; o <<= 1) {
            s0 += __shfl_xor_sync(0xFFFFFFFFu, s0, o);
            q0 += __shfl_xor_sync(0xFFFFFFFFu, q0, o);
            s1 += __shfl_xor_sync(0xFFFFFFFFu, s1, o);
            q1 += __shfl_xor_sync(0xFFFFFFFFu, q1, o);
        }
        if (tig == 0) {
            int rl = mrow + mt * 16 + g;
            atomicAdd(&s_sum[rl], s0);
            atomicAdd(&s_sq[rl], q0);
            atomicAdd(&s_sum[rl + 8], s1);
            atomicAdd(&s_sq[rl + 8], q1);
        }
    }
    __syncthreads();

#pragma unroll
    for (int mt = 0; mt < 2; mt++) {
        int rl = mrow + mt * 16 + g;
        float mu0 = s_sum[rl] * (1.0f / 128.0f);
        float v0  = s_sq[rl] * (1.0f / 128.0f) - mu0 * mu0;
        float rs0 = rsqrtf(v0 + 1e-5f);
        float mu1 = s_sum[rl + 8] * (1.0f / 128.0f);
        float v1  = s_sq[rl + 8] * (1.0f / 128.0f) - mu1 * mu1;
        float rs1 = rsqrtf(v1 + 1e-5f);
        float* h0 = g_h + (size_t)(n0 + rl) * H;
        float* h1 = g_h + (size_t)(n0 + rl + 8) * H;
#pragma unroll
        for (int nt = 0; nt < 8; nt++) {
            int colg = ncol + nt * 8 + tig * 2;
            float gx = s_g[colg], gy = s_g[colg + 1];
            float bx = s_b[colg], by = s_b[colg + 1];
            float y0 = fmaxf((acc[mt][nt][0] - mu0) * rs0 * gx + bx, 0.f);
            float y1 = fmaxf((acc[mt][nt][1] - mu0) * rs0 * gy + by, 0.f);
            float y2 = fmaxf((acc[mt][nt][2] - mu1) * rs1 * gx + bx, 0.f);
            float y3 = fmaxf((acc[mt][nt][3] - mu1) * rs1 * gy + by, 0.f);
            if (addres) {
                float2 o0 = *(float2*)(h0 + colg);
                float2 o1 = *(float2*)(h1 + colg);
                y0 += o0.x; y1 += o0.y; y2 += o1.x; y3 += o1.y;
            }
            *(float2*)(h0 + colg) = make_float2(y0, y1);
            *(float2*)(h1 + colg) = make_float2(y2, y3);
        }
    }
}

// ---------------- output head: relu(h @ h1_w + h1_b) @ h2_w + h2_b ---------
__global__ void k_head(const float* __restrict__ w1, const float* __restrict__ b1,
                       const float* __restrict__ w2, const float* __restrict__ b2,
                       float* __restrict__ out) {
    __shared__ float sm[12288];
    int tid = threadIdx.x;
    int n0  = blockIdx.x * 64;
    int ty = tid >> 4, tx = tid & 15;
    float acc[4][8] = {};

    float* Ws = sm;
    float* Xt = sm + 8192;
    float4* Ws4 = (float4*)Ws;
    const float4* Xt4 = (const float4*)Xt;

    for (int s = 0; s < 2; s++) {
        int kb = s * 64;
        __syncthreads();
#pragma unroll
        for (int i = 0; i < 8; i++) {
            int q = i * 256 + tid;
            Ws4[q] = ((const float4*)w1)[kb * 32 + q];
        }
#pragma unroll
        for (int i = 0; i < 4; i++) {
            int q = i * 256 + tid;
            int node = q & 63;
            int kq   = q >> 6;
            float4 v = ((const float4*)g_h)[(size_t)(n0 + node) * 32 + kb / 4 + kq];
            Xt[(kq * 4 + 0) * 64 + node] = v.x;
            Xt[(kq * 4 + 1) * 64 + node] = v.y;
            Xt[(kq * 4 + 2) * 64 + node] = v.z;
            Xt[(kq * 4 + 3) * 64 + node] = v.w;
        }
        __syncthreads();
#pragma unroll 8
        for (int k = 0; k < 64; k++) {
            float4 xa = Xt4[k * 16 + ty];
            float4 wa = Ws4[k * 32 + tx];
            float4 wb = Ws4[k * 32 + 16 + tx];
            float xv[4] = {xa.x, xa.y, xa.z, xa.w};
            float wv[8] = {wa.x, wa.y, wa.z, wa.w, wb.x, wb.y, wb.z, wb.w};
#pragma unroll
            for (int i = 0; i < 4; i++)
#pragma unroll
                for (int j = 0; j < 8; j++) acc[i][j] += xv[i] * wv[j];
        }
    }

    __syncthreads();
    float* Ts  = sm;              // [64][132]
    float* W2t = sm + 64 * 132;   // [8][128]
    float4 b1a = ((const float4*)b1)[tx];
    float4 b1b = ((const float4*)b1)[16 + tx];
#pragma unroll
    for (int i = 0; i < 4; i++) {
        int node = ty * 4 + i;
        float4 t1 = make_float4(fmaxf(acc[i][0] + b1a.x, 0.f), fmaxf(acc[i][1] + b1a.y, 0.f),
                                fmaxf(acc[i][2] + b1a.z, 0.f), fmaxf(acc[i][3] + b1a.w, 0.f));
        float4 t2 = make_float4(fmaxf(acc[i][4] + b1b.x, 0.f), fmaxf(acc[i][5] + b1b.y, 0.f),
                                fmaxf(acc[i][6] + b1b.z, 0.f), fmaxf(acc[i][7] + b1b.w, 0.f));
        ((float4*)(Ts + node * 132))[tx]      = t1;
        ((float4*)(Ts + node * 132))[16 + tx] = t2;
    }
#pragma unroll
    for (int i = 0; i < 4; i++) {
        int idx = i * 256 + tid;
        int k = idx >> 3, o = idx & 7;
        W2t[o * 128 + k] = w2[idx];
    }
    __syncthreads();

#pragma unroll
    for (int p = 0; p < 2; p++) {
        int idx = tid * 2 + p;
        int n = idx >> 3, o = idx & 7;
        int gn = n0 + n;
        float a = 0.f;
        const float4* tr = (const float4*)(Ts + n * 132);
        const float4* wr = (const float4*)(W2t + o * 128);
#pragma unroll
        for (int kq = 0; kq < 32; kq++) {
            float4 t4 = tr[kq];
            float4 w4 = wr[kq];
            a += t4.x * w4.x + t4.y * w4.y + t4.z * w4.z + t4.w * w4.w;
        }
        if (gn < N_NODES) out[(size_t)gn * OUT_DIM + o] = a + b2[o];
    }
}

// ---------------------------------------------------------------------------
// kernel_launch: KERNEL LAUNCHES ONLY (capture-safe; all static smem).
extern "C" void kernel_launch(void* const* d_in, const int* in_sizes, int n_in,
                              void* d_out, int out_size) {
    const float* x      = (const float*)d_in[0];
    const int*   ei     = (const int*)d_in[1];
    const int*   et     = (const int*)d_in[2];
    const float* in_w   = (const float*)d_in[3];
    const float* in_b   = (const float*)d_in[4];
    const float* bases  = (const float*)d_in[5];
    const float* comp   = (const float*)d_in[6];
    const float* root   = (const float*)d_in[7];
    const float* conv_b = (const float*)d_in[8];
    const float* ln_g   = (const float*)d_in[9];
    const float* ln_b   = (const float*)d_in[10];
    const float* h1_w   = (const float*)d_in[11];
    const float* h1_b   = (const float*)d_in[12];
    const float* h2_w   = (const float*)d_in[13];
    const float* h2_b   = (const float*)d_in[14];
    float* out = (float*)d_out;

    // input projection + weight prep
    k_proj<<<NPAD / 64, 256>>>(x, in_w, in_b);
    k_prep<<<(L_LAYERS * KTOT * 128 + 255) / 256, 256>>>(bases, root);

    // CSR build (graph-constant, rebuilt per call; inv folded into scanA)
    k_zero_cnt<<<(NPAD * R_REL + 255) / 256, 256>>>();
    k_count<<<(E_EDGES + 255) / 256, 256>>>(ei, et);
    k_scanA<<<NSCANBLK, 256>>>();
    k_scanB<<<1, 128>>>();
    k_scanC<<<(NPAD + 255) / 256, 256>>>();
    k_fill<<<(E_EDGES + 255) / 256, 256>>>(ei, et);

    for (int l = 0; l < L_LAYERS; l++) {
        k_gather<<<NPAD / 8, 256>>>(comp + (size_t)l * R_REL * B_BASES);
        k_conv_fused<<<NPAD / 128, 256>>>(l, conv_b + (size_t)l * H,
                                          ln_g + (size_t)l * H, ln_b + (size_t)l * H,
                                          l > 0 ? 1 : 0);
    }

    k_head<<<(N_NODES + 63) / 64, 256>>>(h1_w, h1_b, h2_w, h2_b, out);
}

// round 16
// speedup vs baseline: 1.0358x; 1.0358x over previous
#include <cuda_runtime.h>
#include <cuda_bf16.h>
#include <cstdint>

// Problem constants
#define N_NODES 100000
#define NPAD    100096          // multiple of 128
#define E_EDGES 1600000
#define F_INDIM 64
#define H       128
#define OUT_DIM 8
#define R_REL   10
#define B_BASES 4
#define L_LAYERS 3
#define KTOT    640             // 4*128 (bases) + 128 (root)
#define NSCANBLK 98             // ceil(NPAD/1024)

// ---------------- scratch (static __device__, zero-initialized at load) ----
__device__ float g_h[(size_t)NPAD * H];
__device__ float g_C[(size_t)B_BASES * NPAD * H];    // [b][n][H]
__device__ int   g_cnt[NPAD * R_REL];
__device__ float g_inv[NPAD * R_REL];
__device__ int   g_rowptr[NPAD + 1];
__device__ int   g_cursor[NPAD];
__device__ int   g_adj[E_EDGES];                     // src | (rtype<<20)
__device__ int   g_bs[NSCANBLK];
// transposed bf16 hi/lo weights: [l][n_out=128][k=640]
__device__ __nv_bfloat16 g_Whi[(size_t)L_LAYERS * 128 * KTOT];
__device__ __nv_bfloat16 g_Wlo[(size_t)L_LAYERS * 128 * KTOT];

__device__ __forceinline__ uint32_t pack_bf16(float a, float b) {
    __nv_bfloat162 t = __floats2bfloat162_rn(a, b);
    return *(uint32_t*)&t;
}

#define MMA16816(d, a, b) \
    asm volatile("mma.sync.aligned.m16n8k16.row.col.f32.bf16.bf16.f32 " \
        "{%0,%1,%2,%3}, {%4,%5,%6,%7}, {%8,%9}, {%0,%1,%2,%3};" \
        : "+f"((d)[0]), "+f"((d)[1]), "+f"((d)[2]), "+f"((d)[3]) \
        : "r"((a)[0]), "r"((a)[1]), "r"((a)[2]), "r"((a)[3]), \
          "r"((b)[0]), "r"((b)[1]))

#define LDSM4(r0, r1, r2, r3, addr) \
    asm volatile("ldmatrix.sync.aligned.m8n8.x4.shared.b16 {%0,%1,%2,%3}, [%4];" \
        : "=r"(r0), "=r"(r1), "=r"(r2), "=r"(r3) : "r"(addr))

// ---------------- input projection: h = x @ in_w + in_b  (K=64) ------------
__global__ void k_proj(const float* __restrict__ x, const float* __restrict__ w,
                       const float* __restrict__ b) {
    __shared__ float sm[12288];
    float* Ws = sm;              // [64][128]
    float* Xt = sm + 64 * 128;   // [k=64][node=64]
    int tid = threadIdx.x;
    int n0  = blockIdx.x * 64;

    float4* Ws4 = (float4*)Ws;
    const float4* w4 = (const float4*)w;
#pragma unroll
    for (int i = 0; i < 8; i++) Ws4[i * 256 + tid] = w4[i * 256 + tid];

#pragma unroll
    for (int i = 0; i < 4; i++) {
        int q = i * 256 + tid;
        int node = q & 63;
        int kq   = q >> 6;
        float4 v = make_float4(0.f, 0.f, 0.f, 0.f);
        int n = n0 + node;
        if (n < N_NODES) v = ((const float4*)x)[(size_t)n * 16 + kq];
        Xt[(kq * 4 + 0) * 64 + node] = v.x;
        Xt[(kq * 4 + 1) * 64 + node] = v.y;
        Xt[(kq * 4 + 2) * 64 + node] = v.z;
        Xt[(kq * 4 + 3) * 64 + node] = v.w;
    }
    __syncthreads();

    int ty = tid >> 4, tx = tid & 15;
    float acc[4][8] = {};
    const float4* Xt4 = (const float4*)Xt;
#pragma unroll 8
    for (int k = 0; k < 64; k++) {
        float4 xa = Xt4[k * 16 + ty];
        float4 wa = Ws4[k * 32 + tx];
        float4 wb = Ws4[k * 32 + 16 + tx];
        float xv[4] = {xa.x, xa.y, xa.z, xa.w};
        float wv[8] = {wa.x, wa.y, wa.z, wa.w, wb.x, wb.y, wb.z, wb.w};
#pragma unroll
        for (int i = 0; i < 4; i++)
#pragma unroll
            for (int j = 0; j < 8; j++) acc[i][j] += xv[i] * wv[j];
    }

    float4 ba = ((const float4*)b)[tx];
    float4 bb = ((const float4*)b)[16 + tx];
#pragma unroll
    for (int i = 0; i < 4; i++) {
        int n = n0 + ty * 4 + i;
        float4 o1 = make_float4(acc[i][0] + ba.x, acc[i][1] + ba.y,
                                acc[i][2] + ba.z, acc[i][3] + ba.w);
        float4 o2 = make_float4(acc[i][4] + bb.x, acc[i][5] + bb.y,
                                acc[i][6] + bb.z, acc[i][7] + bb.w);
        ((float4*)g_h)[(size_t)n * 32 + tx]      = o1;
        ((float4*)g_h)[(size_t)n * 32 + 16 + tx] = o2;
    }
}

// ---------------- weight prep: transpose + bf16 hi/lo split (once/call) ----
__global__ void k_prep(const float* __restrict__ bases, const float* __restrict__ root) {
    int i = blockIdx.x * 256 + threadIdx.x;
    if (i >= L_LAYERS * KTOT * 128) return;
    int n = i & 127;
    int k = (i >> 7) % KTOT;
    int l = i / (KTOT * 128);
    float w;
    if (k < 512)
        w = bases[((((size_t)l * B_BASES + (k >> 7)) * H) + (k & 127)) * H + n];
    else
        w = root[((size_t)l * H + (k - 512)) * H + n];
    __nv_bfloat16 hi = __float2bfloat16(w);
    __nv_bfloat16 lo = __float2bfloat16(w - __bfloat162float(hi));
    size_t idx = ((size_t)l * 128 + n) * KTOT + k;
    g_Whi[idx] = hi;
    g_Wlo[idx] = lo;
}

// ---------------- CSR build ------------------------------------------------
__global__ void k_zero_cnt() {
    int i = blockIdx.x * 256 + threadIdx.x;
    if (i < NPAD * R_REL) g_cnt[i] = 0;
}

__global__ void k_count(const int* __restrict__ ei, const int* __restrict__ et) {
    int e = blockIdx.x * 256 + threadIdx.x;
    if (e < E_EDGES) {
        int d = ei[E_EDGES + e];
        int r = et[e];
        atomicAdd(&g_cnt[d * R_REL + r], 1);
    }
}

// scan stage A: per-1024-chunk exclusive scan of degrees (deg = sum_r cnt).
// Also writes g_inv inline (folded former k_inv kernel).
__global__ void k_scanA() {
    __shared__ int sm[256];
    int t = threadIdx.x;
    int base = blockIdx.x * 1024 + t * 4;
    int d[4];
#pragma unroll
    for (int j = 0; j < 4; j++) {
        int idx = base + j;
        int s = 0;
        if (idx < NPAD) {
#pragma unroll
            for (int r = 0; r < R_REL; r++) {
                int c = g_cnt[idx * R_REL + r];
                s += c;
                g_inv[idx * R_REL + r] = 1.0f / (float)(c > 1 ? c : 1);
            }
        }
        d[j] = s;
    }
    int tot = d[0] + d[1] + d[2] + d[3];
    sm[t] = tot;
    __syncthreads();
    int run = tot;
    for (int o = 1; o < 256; o <<= 1) {
        int v = (t >= o) ? sm[t - o] : 0;
        __syncthreads();
        sm[t] += v;
        __syncthreads();
    }
    int excl = sm[t] - run;
    if (t == 255) g_bs[blockIdx.x] = sm[255];
    int acc = excl;
#pragma unroll
    for (int j = 0; j < 4; j++) {
        int idx = base + j;
        if (idx < NPAD) g_rowptr[idx] = acc;
        acc += d[j];
    }
}

// scan stage B: exclusive scan of the 98 block sums (single block)
__global__ void k_scanB() {
    __shared__ int sm[128];
    int t = threadIdx.x;
    int v = (t < NSCANBLK) ? g_bs[t] : 0;
    sm[t] = v;
    __syncthreads();
    for (int o = 1; o < 128; o <<= 1) {
        int u = (t >= o) ? sm[t - o] : 0;
        __syncthreads();
        sm[t] += u;
        __syncthreads();
    }
    if (t < NSCANBLK) g_bs[t] = sm[t] - v;
}

// scan stage C: add block offsets, init cursor, set sentinel
__global__ void k_scanC() {
    int i = blockIdx.x * 256 + threadIdx.x;
    if (i < NPAD) {
        int v = g_rowptr[i] + g_bs[i >> 10];
        g_rowptr[i] = v;
        g_cursor[i] = v;
    }
    if (i == 0) g_rowptr[NPAD] = E_EDGES;
}

__global__ void k_fill(const int* __restrict__ ei, const int* __restrict__ et) {
    int e = blockIdx.x * 256 + threadIdx.x;
    if (e < E_EDGES) {
        int s = ei[e];
        int d = ei[E_EDGES + e];
        int r = et[e];
        int pos = atomicAdd(&g_cursor[d], 1);
        g_adj[pos] = s | (r << 20);
    }
}

// ---------------- gather-aggregate: C[b][n][:] = sum_e comp[r,b]/cnt * h[src]
// one warp per dst node; 4-edge unroll (measured-best occupancy/MLP balance).
__global__ void __launch_bounds__(256) k_gather(const float* __restrict__ comp_l) {
    __shared__ float scomp[R_REL * B_BASES];
    if (threadIdx.x < R_REL * B_BASES) scomp[threadIdx.x] = comp_l[threadIdx.x];
    __syncthreads();
    int wid = threadIdx.x >> 5, lane = threadIdx.x & 31;
    int n = blockIdx.x * 8 + wid;
    if (n >= NPAD) return;
    int beg = g_rowptr[n], end = g_rowptr[n + 1];

    float myinv = (lane < R_REL && n < N_NODES) ? g_inv[n * R_REL + lane] : 0.f;

    const float4* h4 = (const float4*)g_h;
    float4 c[B_BASES];
#pragma unroll
    for (int b = 0; b < B_BASES; b++) c[b] = make_float4(0.f, 0.f, 0.f, 0.f);

    int e = beg;
    for (; e + 3 < end; e += 4) {
        int p0 = g_adj[e], p1 = g_adj[e + 1], p2 = g_adj[e + 2], p3 = g_adj[e + 3];
        int s0 = p0 & 0xFFFFF, r0 = p0 >> 20;
        int s1 = p1 & 0xFFFFF, r1 = p1 >> 20;
        int s2 = p2 & 0xFFFFF, r2 = p2 >> 20;
        int s3 = p3 & 0xFFFFF, r3 = p3 >> 20;
        float4 v0 = h4[(size_t)s0 * 32 + lane];
        float4 v1 = h4[(size_t)s1 * 32 + lane];
        float4 v2 = h4[(size_t)s2 * 32 + lane];
        float4 v3 = h4[(size_t)s3 * 32 + lane];
        float i0 = __shfl_sync(0xFFFFFFFFu, myinv, r0);
        float i1 = __shfl_sync(0xFFFFFFFFu, myinv, r1);
        float i2 = __shfl_sync(0xFFFFFFFFu, myinv, r2);
        float i3 = __shfl_sync(0xFFFFFFFFu, myinv, r3);
#pragma unroll
        for (int b = 0; b < B_BASES; b++) {
            float w0 = scomp[r0 * B_BASES + b] * i0;
            float w1 = scomp[r1 * B_BASES + b] * i1;
            float w2 = scomp[r2 * B_BASES + b] * i2;
            float w3 = scomp[r3 * B_BASES + b] * i3;
            c[b].x += w0 * v0.x + w1 * v1.x + w2 * v2.x + w3 * v3.x;
            c[b].y += w0 * v0.y + w1 * v1.y + w2 * v2.y + w3 * v3.y;
            c[b].z += w0 * v0.z + w1 * v1.z + w2 * v2.z + w3 * v3.z;
            c[b].w += w0 * v0.w + w1 * v1.w + w2 * v2.w + w3 * v3.w;
        }
    }
    for (; e < end; e++) {
        int p0 = g_adj[e];
        int s0 = p0 & 0xFFFFF, r0 = p0 >> 20;
        float4 v0 = h4[(size_t)s0 * 32 + lane];
        float i0 = __shfl_sync(0xFFFFFFFFu, myinv, r0);
#pragma unroll
        for (int b = 0; b < B_BASES; b++) {
            float w0 = scomp[r0 * B_BASES + b] * i0;
            c[b].x += w0 * v0.x;
            c[b].y += w0 * v0.y;
            c[b].z += w0 * v0.z;
            c[b].w += w0 * v0.w;
        }
    }

    float4* C4 = (float4*)g_C;
#pragma unroll
    for (int b = 0; b < B_BASES; b++)
        C4[((size_t)b * NPAD + n) * 32 + lane] = c[b];
}

// ---------------- fused conv GEMM + bias + LayerNorm + ReLU + residual -----
// Per CTA: D[128 nodes, 128 out] = X[128, 640] @ W^T, X = [C0..C3, h] fp32,
// then h_new = (l>0 ? h_old : 0) + relu(LN(D + conv_b)), written to g_h.
// Mainloop is software-pipelined: chunk kc+1's global loads (X fp32 + W bf16)
// are prefetched into registers before chunk kc's MMA section.
__global__ void __launch_bounds__(256, 2)
k_conv_fused(int l, const float* __restrict__ cb,
             const float* __restrict__ lng, const float* __restrict__ lnb,
             int addres) {
    __shared__ __nv_bfloat16 sXhi[128][40];
    __shared__ __nv_bfloat16 sXlo[128][40];
    __shared__ __nv_bfloat16 sWhi[128][40];
    __shared__ __nv_bfloat16 sWlo[128][40];
    __shared__ float s_sum[128], s_sq[128];
    __shared__ float s_g[128], s_b[128], s_cb[128];

    int tid  = threadIdx.x;
    int warp = tid >> 5, lane = tid & 31;
    int g = lane >> 2, tig = lane & 3;
    int n0   = blockIdx.x * 128;
    int mrow = (warp >> 1) * 32;
    int ncol = (warp & 1) * 64;

    if (tid < 128) {
        s_sum[tid] = 0.f;
        s_sq[tid]  = 0.f;
        s_g[tid]   = lng[tid];
        s_b[tid]   = lnb[tid];
        s_cb[tid]  = cb[tid];
    }

    uint32_t sXhi_b = (uint32_t)__cvta_generic_to_shared(&sXhi[0][0]);
    uint32_t sXlo_b = (uint32_t)__cvta_generic_to_shared(&sXlo[0][0]);
    uint32_t sWhi_b = (uint32_t)__cvta_generic_to_shared(&sWhi[0][0]);
    uint32_t sWlo_b = (uint32_t)__cvta_generic_to_shared(&sWlo[0][0]);

    // ldmatrix per-lane byte offsets (within the [128][40] bf16 arrays)
    uint32_t a_off = (uint32_t)(((mrow + ((lane >> 3) & 1) * 8 + (lane & 7)) * 40
                                 + (lane >> 4) * 8) * 2);
    uint32_t b_off = (uint32_t)(((ncol + ((lane >> 4) & 1) * 8 + (lane & 7)) * 40
                                 + ((lane >> 3) & 1) * 8) * 2);

    float acc[2][8][4];
#pragma unroll
    for (int mt = 0; mt < 2; mt++)
#pragma unroll
        for (int nt = 0; nt < 8; nt++)
#pragma unroll
            for (int q = 0; q < 4; q++) acc[mt][nt][q] = 0.f;

    const __nv_bfloat16* whi = g_Whi + (size_t)l * 128 * KTOT;
    const __nv_bfloat16* wlo = g_Wlo + (size_t)l * 128 * KTOT;

    int row = tid >> 1, half = tid & 1;

    // prefetch chunk 0
    float4 px[4];
    uint4  pwh[2], pwl[2];
    {
        const float4* xs4 = (const float4*)(g_C + ((size_t)0 * NPAD + (n0 + row)) * H
                                            + half * 16);
#pragma unroll
        for (int j = 0; j < 4; j++) px[j] = xs4[j];
        const uint4* wh4 = (const uint4*)(whi + (size_t)row * KTOT + half * 16);
        const uint4* wl4 = (const uint4*)(wlo + (size_t)row * KTOT + half * 16);
        pwh[0] = wh4[0]; pwh[1] = wh4[1];
        pwl[0] = wl4[0]; pwl[1] = wl4[1];
    }

    for (int kc = 0; kc < 20; kc++) {
        __syncthreads();   // previous chunk's MMA reads complete
        // store prefetched X (with bf16 hi/lo split) and W to smem
#pragma unroll
        for (int j = 0; j < 4; j++) {
            float4 v = px[j];
            float hx = __bfloat162float(__float2bfloat16(v.x));
            float hy = __bfloat162float(__float2bfloat16(v.y));
            float hz = __bfloat162float(__float2bfloat16(v.z));
            float hw = __bfloat162float(__float2bfloat16(v.w));
            int col = half * 16 + j * 4;
            *(uint2*)&sXhi[row][col] = make_uint2(pack_bf16(v.x, v.y), pack_bf16(v.z, v.w));
            *(uint2*)&sXlo[row][col] = make_uint2(pack_bf16(v.x - hx, v.y - hy),
                                                  pack_bf16(v.z - hz, v.w - hw));
        }
        *(uint4*)&sWhi[row][half * 16]     = pwh[0];
        *(uint4*)&sWhi[row][half * 16 + 8] = pwh[1];
        *(uint4*)&sWlo[row][half * 16]     = pwl[0];
        *(uint4*)&sWlo[row][half * 16 + 8] = pwl[1];
        __syncthreads();

        // prefetch chunk kc+1 (overlaps the MMA section below)
        if (kc < 19) {
            int kn = kc + 1;
            int c = kn >> 2, koff = (kn & 3) * 32;
            const float* xs = (c < 4)
                ? g_C + ((size_t)c * NPAD + (n0 + row)) * H + koff + half * 16
                : g_h + (size_t)(n0 + row) * H + koff + half * 16;
            const float4* xs4 = (const float4*)xs;
#pragma unroll
            for (int j = 0; j < 4; j++) px[j] = xs4[j];
            const uint4* wh4 = (const uint4*)(whi + (size_t)row * KTOT + kn * 32 + half * 16);
            const uint4* wl4 = (const uint4*)(wlo + (size_t)row * KTOT + kn * 32 + half * 16);
            pwh[0] = wh4[0]; pwh[1] = wh4[1];
            pwl[0] = wl4[0]; pwl[1] = wl4[1];
        }

#pragma unroll
        for (int ks = 0; ks < 32; ks += 16) {
            uint32_t ah[2][4], al[2][4], bb[8][2];
            uint32_t ksb = (uint32_t)(ks * 2);
#pragma unroll
            for (int mt = 0; mt < 2; mt++) {
                uint32_t mo = (uint32_t)(mt * 16 * 40 * 2) + ksb;
                LDSM4(ah[mt][0], ah[mt][1], ah[mt][2], ah[mt][3], sXhi_b + a_off + mo);
                LDSM4(al[mt][0], al[mt][1], al[mt][2], al[mt][3], sXlo_b + a_off + mo);
            }
#pragma unroll
            for (int np = 0; np < 4; np++) {
                uint32_t no = (uint32_t)(np * 16 * 40 * 2) + ksb;
                LDSM4(bb[2 * np][0], bb[2 * np][1], bb[2 * np + 1][0], bb[2 * np + 1][1],
                      sWhi_b + b_off + no);
            }
#pragma unroll
            for (int mt = 0; mt < 2; mt++)
#pragma unroll
                for (int nt = 0; nt < 8; nt++) {
                    MMA16816(acc[mt][nt], ah[mt], bb[nt]);   // hi*hi
                    MMA16816(acc[mt][nt], al[mt], bb[nt]);   // lo*hi
                }
#pragma unroll
            for (int np = 0; np < 4; np++) {
                uint32_t no = (uint32_t)(np * 16 * 40 * 2) + ksb;
                LDSM4(bb[2 * np][0], bb[2 * np][1], bb[2 * np + 1][0], bb[2 * np + 1][1],
                      sWlo_b + b_off + no);
            }
#pragma unroll
            for (int mt = 0; mt < 2; mt++)
#pragma unroll
                for (int nt = 0; nt < 8; nt++)
                    MMA16816(acc[mt][nt], ah[mt], bb[nt]);   // hi*lo
        }
    }

    // ---- fused epilogue: bias -> LN stats -> LN+ReLU+residual -> g_h ----
#pragma unroll
    for (int mt = 0; mt < 2; mt++) {
        float s0 = 0.f, q0 = 0.f, s1 = 0.f, q1 = 0.f;
#pragma unroll
        for (int nt = 0; nt < 8; nt++) {
            int colg = ncol + nt * 8 + tig * 2;
            float bx = s_cb[colg], by = s_cb[colg + 1];
            float a0 = acc[mt][nt][0] + bx, a1 = acc[mt][nt][1] + by;
            float a2 = acc[mt][nt][2] + bx, a3 = acc[mt][nt][3] + by;
            acc[mt][nt][0] = a0; acc[mt][nt][1] = a1;
            acc[mt][nt][2] = a2; acc[mt][nt][3] = a3;
            s0 += a0 + a1; q0 += a0 * a0 + a1 * a1;
            s1 += a2 + a3; q1 += a2 * a2 + a3 * a3;
        }
#pragma unroll
        for (int o = 1; o <= 2; o <<= 1) {
            s0 += __shfl_xor_sync(0xFFFFFFFFu, s0, o);
            q0 += __shfl_xor_sync(0xFFFFFFFFu, q0, o);
            s1 += __shfl_xor_sync(0xFFFFFFFFu, s1, o);
            q1 += __shfl_xor_sync(0xFFFFFFFFu, q1, o);
        }
        if (tig == 0) {
            int rl = mrow + mt * 16 + g;
            atomicAdd(&s_sum[rl], s0);
            atomicAdd(&s_sq[rl], q0);
            atomicAdd(&s_sum[rl + 8], s1);
            atomicAdd(&s_sq[rl + 8], q1);
        }
    }
    __syncthreads();

#pragma unroll
    for (int mt = 0; mt < 2; mt++) {
        int rl = mrow + mt * 16 + g;
        float mu0 = s_sum[rl] * (1.0f / 128.0f);
        float v0  = s_sq[rl] * (1.0f / 128.0f) - mu0 * mu0;
        float rs0 = rsqrtf(v0 + 1e-5f);
        float mu1 = s_sum[rl + 8] * (1.0f / 128.0f);
        float v1  = s_sq[rl + 8] * (1.0f / 128.0f) - mu1 * mu1;
        float rs1 = rsqrtf(v1 + 1e-5f);
        float* h0 = g_h + (size_t)(n0 + rl) * H;
        float* h1 = g_h + (size_t)(n0 + rl + 8) * H;
#pragma unroll
        for (int nt = 0; nt < 8; nt++) {
            int colg = ncol + nt * 8 + tig * 2;
            float gx = s_g[colg], gy = s_g[colg + 1];
            float bx = s_b[colg], by = s_b[colg + 1];
            float y0 = fmaxf((acc[mt][nt][0] - mu0) * rs0 * gx + bx, 0.f);
            float y1 = fmaxf((acc[mt][nt][1] - mu0) * rs0 * gy + by, 0.f);
            float y2 = fmaxf((acc[mt][nt][2] - mu1) * rs1 * gx + bx, 0.f);
            float y3 = fmaxf((acc[mt][nt][3] - mu1) * rs1 * gy + by, 0.f);
            if (addres) {
                float2 o0 = *(float2*)(h0 + colg);
                float2 o1 = *(float2*)(h1 + colg);
                y0 += o0.x; y1 += o0.y; y2 += o1.x; y3 += o1.y;
            }
            *(float2*)(h0 + colg) = make_float2(y0, y1);
            *(float2*)(h1 + colg) = make_float2(y2, y3);
        }
    }
}

// ---------------- output head: relu(h @ h1_w + h1_b) @ h2_w + h2_b ---------
__global__ void k_head(const float* __restrict__ w1, const float* __restrict__ b1,
                       const float* __restrict__ w2, const float* __restrict__ b2,
                       float* __restrict__ out) {
    __shared__ float sm[12288];
    int tid = threadIdx.x;
    int n0  = blockIdx.x * 64;
    int ty = tid >> 4, tx = tid & 15;
    float acc[4][8] = {};

    float* Ws = sm;
    float* Xt = sm + 8192;
    float4* Ws4 = (float4*)Ws;
    const float4* Xt4 = (const float4*)Xt;

    for (int s = 0; s < 2; s++) {
        int kb = s * 64;
        __syncthreads();
#pragma unroll
        for (int i = 0; i < 8; i++) {
            int q = i * 256 + tid;
            Ws4[q] = ((const float4*)w1)[kb * 32 + q];
        }
#pragma unroll
        for (int i = 0; i < 4; i++) {
            int q = i * 256 + tid;
            int node = q & 63;
            int kq   = q >> 6;
            float4 v = ((const float4*)g_h)[(size_t)(n0 + node) * 32 + kb / 4 + kq];
            Xt[(kq * 4 + 0) * 64 + node] = v.x;
            Xt[(kq * 4 + 1) * 64 + node] = v.y;
            Xt[(kq * 4 + 2) * 64 + node] = v.z;
            Xt[(kq * 4 + 3) * 64 + node] = v.w;
        }
        __syncthreads();
#pragma unroll 8
        for (int k = 0; k < 64; k++) {
            float4 xa = Xt4[k * 16 + ty];
            float4 wa = Ws4[k * 32 + tx];
            float4 wb = Ws4[k * 32 + 16 + tx];
            float xv[4] = {xa.x, xa.y, xa.z, xa.w};
            float wv[8] = {wa.x, wa.y, wa.z, wa.w, wb.x, wb.y, wb.z, wb.w};
#pragma unroll
            for (int i = 0; i < 4; i++)
#pragma unroll
                for (int j = 0; j < 8; j++) acc[i][j] += xv[i] * wv[j];
        }
    }

    __syncthreads();
    float* Ts  = sm;              // [64][132]
    float* W2t = sm + 64 * 132;   // [8][128]
    float4 b1a = ((const float4*)b1)[tx];
    float4 b1b = ((const float4*)b1)[16 + tx];
#pragma unroll
    for (int i = 0; i < 4; i++) {
        int node = ty * 4 + i;
        float4 t1 = make_float4(fmaxf(acc[i][0] + b1a.x, 0.f), fmaxf(acc[i][1] + b1a.y, 0.f),
                                fmaxf(acc[i][2] + b1a.z, 0.f), fmaxf(acc[i][3] + b1a.w, 0.f));
        float4 t2 = make_float4(fmaxf(acc[i][4] + b1b.x, 0.f), fmaxf(acc[i][5] + b1b.y, 0.f),
                                fmaxf(acc[i][6] + b1b.z, 0.f), fmaxf(acc[i][7] + b1b.w, 0.f));
        ((float4*)(Ts + node * 132))[tx]      = t1;
        ((float4*)(Ts + node * 132))[16 + tx] = t2;
    }
#pragma unroll
    for (int i = 0; i < 4; i++) {
        int idx = i * 256 + tid;
        int k = idx >> 3, o = idx & 7;
        W2t[o * 128 + k] = w2[idx];
    }
    __syncthreads();

#pragma unroll
    for (int p = 0; p < 2; p++) {
        int idx = tid * 2 + p;
        int n = idx >> 3, o = idx & 7;
        int gn = n0 + n;
        float a = 0.f;
        const float4* tr = (const float4*)(Ts + n * 132);
        const float4* wr = (const float4*)(W2t + o * 128);
#pragma unroll
        for (int kq = 0; kq < 32; kq++) {
            float4 t4 = tr[kq];
            float4 w4 = wr[kq];
            a += t4.x * w4.x + t4.y * w4.y + t4.z * w4.z + t4.w * w4.w;
        }
        if (gn < N_NODES) out[(size_t)gn * OUT_DIM + o] = a + b2[o];
    }
}

// ---------------------------------------------------------------------------
// kernel_launch: KERNEL LAUNCHES ONLY (capture-safe; all static smem).
extern "C" void kernel_launch(void* const* d_in, const int* in_sizes, int n_in,
                              void* d_out, int out_size) {
    const float* x      = (const float*)d_in[0];
    const int*   ei     = (const int*)d_in[1];
    const int*   et     = (const int*)d_in[2];
    const float* in_w   = (const float*)d_in[3];
    const float* in_b   = (const float*)d_in[4];
    const float* bases  = (const float*)d_in[5];
    const float* comp   = (const float*)d_in[6];
    const float* root   = (const float*)d_in[7];
    const float* conv_b = (const float*)d_in[8];
    const float* ln_g   = (const float*)d_in[9];
    const float* ln_b   = (const float*)d_in[10];
    const float* h1_w   = (const float*)d_in[11];
    const float* h1_b   = (const float*)d_in[12];
    const float* h2_w   = (const float*)d_in[13];
    const float* h2_b   = (const float*)d_in[14];
    float* out = (float*)d_out;

    // input projection + weight prep
    k_proj<<<NPAD / 64, 256>>>(x, in_w, in_b);
    k_prep<<<(L_LAYERS * KTOT * 128 + 255) / 256, 256>>>(bases, root);

    // CSR build (graph-constant, rebuilt per call; inv folded into scanA)
    k_zero_cnt<<<(NPAD * R_REL + 255) / 256, 256>>>();
    k_count<<<(E_EDGES + 255) / 256, 256>>>(ei, et);
    k_scanA<<<NSCANBLK, 256>>>();
    k_scanB<<<1, 128>>>();
    k_scanC<<<(NPAD + 255) / 256, 256>>>();
    k_fill<<<(E_EDGES + 255) / 256, 256>>>(ei, et);

    for (int l = 0; l < L_LAYERS; l++) {
        k_gather<<<NPAD / 8, 256>>>(comp + (size_t)l * R_REL * B_BASES);
        k_conv_fused<<<NPAD / 128, 256>>>(l, conv_b + (size_t)l * H,
                                          ln_g + (size_t)l * H, ln_b + (size_t)l * H,
                                          l > 0 ? 1 : 0);
    }

    k_head<<<(N_NODES + 63) / 64, 256>>>(h1_w, h1_b, h2_w, h2_b, out);
}

// round 17
// speedup vs baseline: 1.2105x; 1.1687x over previous
#include <cuda_runtime.h>
#include <cuda_fp16.h>
#include <cstdint>

// Problem constants
#define N_NODES 100000
#define NPAD    100096          // multiple of 128
#define E_EDGES 1600000
#define F_INDIM 64
#define H       128
#define OUT_DIM 8
#define R_REL   10
#define B_BASES 4
#define L_LAYERS 3
#define KTOT    640             // 4*128 (bases) + 128 (root)
#define NSCANBLK 98             // ceil(NPAD/1024)

// ---------------- scratch (static __device__, zero-initialized at load) ----
__device__ float g_h[(size_t)NPAD * H];
__device__ float g_C[(size_t)B_BASES * NPAD * H];    // [b][n][H]
__device__ int   g_cnt[NPAD * R_REL];
__device__ float g_inv[NPAD * R_REL];
__device__ int   g_rowptr[NPAD + 1];
__device__ int   g_cursor[NPAD];
__device__ int   g_adj[E_EDGES];                     // src | (rtype<<20)
__device__ int   g_bs[NSCANBLK];
// transposed fp16 weights: [l][n_out=128][k=640] (11 mantissa bits)
__device__ __half g_Wf[(size_t)L_LAYERS * 128 * KTOT];

__device__ __forceinline__ uint32_t pack_f16(float a, float b) {
    __half2 t = __floats2half2_rn(a, b);
    return *(uint32_t*)&t;
}

#define MMAF16(d, a, b) \
    asm volatile("mma.sync.aligned.m16n8k16.row.col.f32.f16.f16.f32 " \
        "{%0,%1,%2,%3}, {%4,%5,%6,%7}, {%8,%9}, {%0,%1,%2,%3};" \
        : "+f"((d)[0]), "+f"((d)[1]), "+f"((d)[2]), "+f"((d)[3]) \
        : "r"((a)[0]), "r"((a)[1]), "r"((a)[2]), "r"((a)[3]), \
          "r"((b)[0]), "r"((b)[1]))

#define LDSM4(r0, r1, r2, r3, addr) \
    asm volatile("ldmatrix.sync.aligned.m8n8.x4.shared.b16 {%0,%1,%2,%3}, [%4];" \
        : "=r"(r0), "=r"(r1), "=r"(r2), "=r"(r3) : "r"(addr))

// ---------------- input projection: h = x @ in_w + in_b  (K=64) ------------
__global__ void k_proj(const float* __restrict__ x, const float* __restrict__ w,
                       const float* __restrict__ b) {
    __shared__ float sm[12288];
    float* Ws = sm;              // [64][128]
    float* Xt = sm + 64 * 128;   // [k=64][node=64]
    int tid = threadIdx.x;
    int n0  = blockIdx.x * 64;

    float4* Ws4 = (float4*)Ws;
    const float4* w4 = (const float4*)w;
#pragma unroll
    for (int i = 0; i < 8; i++) Ws4[i * 256 + tid] = w4[i * 256 + tid];

#pragma unroll
    for (int i = 0; i < 4; i++) {
        int q = i * 256 + tid;
        int node = q & 63;
        int kq   = q >> 6;
        float4 v = make_float4(0.f, 0.f, 0.f, 0.f);
        int n = n0 + node;
        if (n < N_NODES) v = ((const float4*)x)[(size_t)n * 16 + kq];
        Xt[(kq * 4 + 0) * 64 + node] = v.x;
        Xt[(kq * 4 + 1) * 64 + node] = v.y;
        Xt[(kq * 4 + 2) * 64 + node] = v.z;
        Xt[(kq * 4 + 3) * 64 + node] = v.w;
    }
    __syncthreads();

    int ty = tid >> 4, tx = tid & 15;
    float acc[4][8] = {};
    const float4* Xt4 = (const float4*)Xt;
#pragma unroll 8
    for (int k = 0; k < 64; k++) {
        float4 xa = Xt4[k * 16 + ty];
        float4 wa = Ws4[k * 32 + tx];
        float4 wb = Ws4[k * 32 + 16 + tx];
        float xv[4] = {xa.x, xa.y, xa.z, xa.w};
        float wv[8] = {wa.x, wa.y, wa.z, wa.w, wb.x, wb.y, wb.z, wb.w};
#pragma unroll
        for (int i = 0; i < 4; i++)
#pragma unroll
            for (int j = 0; j < 8; j++) acc[i][j] += xv[i] * wv[j];
    }

    float4 ba = ((const float4*)b)[tx];
    float4 bb = ((const float4*)b)[16 + tx];
#pragma unroll
    for (int i = 0; i < 4; i++) {
        int n = n0 + ty * 4 + i;
        float4 o1 = make_float4(acc[i][0] + ba.x, acc[i][1] + ba.y,
                                acc[i][2] + ba.z, acc[i][3] + ba.w);
        float4 o2 = make_float4(acc[i][4] + bb.x, acc[i][5] + bb.y,
                                acc[i][6] + bb.z, acc[i][7] + bb.w);
        ((float4*)g_h)[(size_t)n * 32 + tx]      = o1;
        ((float4*)g_h)[(size_t)n * 32 + 16 + tx] = o2;
    }
}

// ---------------- weight prep: transpose + fp16 round (once/call) ----------
__global__ void k_prep(const float* __restrict__ bases, const float* __restrict__ root) {
    int i = blockIdx.x * 256 + threadIdx.x;
    if (i >= L_LAYERS * KTOT * 128) return;
    int n = i & 127;
    int k = (i >> 7) % KTOT;
    int l = i / (KTOT * 128);
    float w;
    if (k < 512)
        w = bases[((((size_t)l * B_BASES + (k >> 7)) * H) + (k & 127)) * H + n];
    else
        w = root[((size_t)l * H + (k - 512)) * H + n];
    g_Wf[((size_t)l * 128 + n) * KTOT + k] = __float2half_rn(w);
}

// ---------------- CSR build ------------------------------------------------
__global__ void k_zero_cnt() {
    int i = blockIdx.x * 256 + threadIdx.x;
    if (i < NPAD * R_REL) g_cnt[i] = 0;
}

__global__ void k_count(const int* __restrict__ ei, const int* __restrict__ et) {
    int e = blockIdx.x * 256 + threadIdx.x;
    if (e < E_EDGES) {
        int d = ei[E_EDGES + e];
        int r = et[e];
        atomicAdd(&g_cnt[d * R_REL + r], 1);
    }
}

// scan stage A: per-1024-chunk exclusive scan of degrees (deg = sum_r cnt).
// Also writes g_inv inline (folded former k_inv kernel).
__global__ void k_scanA() {
    __shared__ int sm[256];
    int t = threadIdx.x;
    int base = blockIdx.x * 1024 + t * 4;
    int d[4];
#pragma unroll
    for (int j = 0; j < 4; j++) {
        int idx = base + j;
        int s = 0;
        if (idx < NPAD) {
#pragma unroll
            for (int r = 0; r < R_REL; r++) {
                int c = g_cnt[idx * R_REL + r];
                s += c;
                g_inv[idx * R_REL + r] = 1.0f / (float)(c > 1 ? c : 1);
            }
        }
        d[j] = s;
    }
    int tot = d[0] + d[1] + d[2] + d[3];
    sm[t] = tot;
    __syncthreads();
    int run = tot;
    for (int o = 1; o < 256; o <<= 1) {
        int v = (t >= o) ? sm[t - o] : 0;
        __syncthreads();
        sm[t] += v;
        __syncthreads();
    }
    int excl = sm[t] - run;
    if (t == 255) g_bs[blockIdx.x] = sm[255];
    int acc = excl;
#pragma unroll
    for (int j = 0; j < 4; j++) {
        int idx = base + j;
        if (idx < NPAD) g_rowptr[idx] = acc;
        acc += d[j];
    }
}

// scan stage B: exclusive scan of the 98 block sums (single block)
__global__ void k_scanB() {
    __shared__ int sm[128];
    int t = threadIdx.x;
    int v = (t < NSCANBLK) ? g_bs[t] : 0;
    sm[t] = v;
    __syncthreads();
    for (int o = 1; o < 128; o <<= 1) {
        int u = (t >= o) ? sm[t - o] : 0;
        __syncthreads();
        sm[t] += u;
        __syncthreads();
    }
    if (t < NSCANBLK) g_bs[t] = sm[t] - v;
}

// scan stage C: add block offsets, init cursor, set sentinel
__global__ void k_scanC() {
    int i = blockIdx.x * 256 + threadIdx.x;
    if (i < NPAD) {
        int v = g_rowptr[i] + g_bs[i >> 10];
        g_rowptr[i] = v;
        g_cursor[i] = v;
    }
    if (i == 0) g_rowptr[NPAD] = E_EDGES;
}

__global__ void k_fill(const int* __restrict__ ei, const int* __restrict__ et) {
    int e = blockIdx.x * 256 + threadIdx.x;
    if (e < E_EDGES) {
        int s = ei[e];
        int d = ei[E_EDGES + e];
        int r = et[e];
        int pos = atomicAdd(&g_cursor[d], 1);
        g_adj[pos] = s | (r << 20);
    }
}

// ---------------- gather-aggregate: C[b][n][:] = sum_e comp[r,b]/cnt * h[src]
// one warp per dst node; 4-edge unroll (measured-best occupancy/MLP balance).
__global__ void __launch_bounds__(256) k_gather(const float* __restrict__ comp_l) {
    __shared__ float scomp[R_REL * B_BASES];
    if (threadIdx.x < R_REL * B_BASES) scomp[threadIdx.x] = comp_l[threadIdx.x];
    __syncthreads();
    int wid = threadIdx.x >> 5, lane = threadIdx.x & 31;
    int n = blockIdx.x * 8 + wid;
    if (n >= NPAD) return;
    int beg = g_rowptr[n], end = g_rowptr[n + 1];

    float myinv = (lane < R_REL && n < N_NODES) ? g_inv[n * R_REL + lane] : 0.f;

    const float4* h4 = (const float4*)g_h;
    float4 c[B_BASES];
#pragma unroll
    for (int b = 0; b < B_BASES; b++) c[b] = make_float4(0.f, 0.f, 0.f, 0.f);

    int e = beg;
    for (; e + 3 < end; e += 4) {
        int p0 = g_adj[e], p1 = g_adj[e + 1], p2 = g_adj[e + 2], p3 = g_adj[e + 3];
        int s0 = p0 & 0xFFFFF, r0 = p0 >> 20;
        int s1 = p1 & 0xFFFFF, r1 = p1 >> 20;
        int s2 = p2 & 0xFFFFF, r2 = p2 >> 20;
        int s3 = p3 & 0xFFFFF, r3 = p3 >> 20;
        float4 v0 = h4[(size_t)s0 * 32 + lane];
        float4 v1 = h4[(size_t)s1 * 32 + lane];
        float4 v2 = h4[(size_t)s2 * 32 + lane];
        float4 v3 = h4[(size_t)s3 * 32 + lane];
        float i0 = __shfl_sync(0xFFFFFFFFu, myinv, r0);
        float i1 = __shfl_sync(0xFFFFFFFFu, myinv, r1);
        float i2 = __shfl_sync(0xFFFFFFFFu, myinv, r2);
        float i3 = __shfl_sync(0xFFFFFFFFu, myinv, r3);
#pragma unroll
        for (int b = 0; b < B_BASES; b++) {
            float w0 = scomp[r0 * B_BASES + b] * i0;
            float w1 = scomp[r1 * B_BASES + b] * i1;
            float w2 = scomp[r2 * B_BASES + b] * i2;
            float w3 = scomp[r3 * B_BASES + b] * i3;
            c[b].x += w0 * v0.x + w1 * v1.x + w2 * v2.x + w3 * v3.x;
            c[b].y += w0 * v0.y + w1 * v1.y + w2 * v2.y + w3 * v3.y;
            c[b].z += w0 * v0.z + w1 * v1.z + w2 * v2.z + w3 * v3.z;
            c[b].w += w0 * v0.w + w1 * v1.w + w2 * v2.w + w3 * v3.w;
        }
    }
    for (; e < end; e++) {
        int p0 = g_adj[e];
        int s0 = p0 & 0xFFFFF, r0 = p0 >> 20;
        float4 v0 = h4[(size_t)s0 * 32 + lane];
        float i0 = __shfl_sync(0xFFFFFFFFu, myinv, r0);
#pragma unroll
        for (int b = 0; b < B_BASES; b++) {
            float w0 = scomp[r0 * B_BASES + b] * i0;
            c[b].x += w0 * v0.x;
            c[b].y += w0 * v0.y;
            c[b].z += w0 * v0.z;
            c[b].w += w0 * v0.w;
        }
    }

    float4* C4 = (float4*)g_C;
#pragma unroll
    for (int b = 0; b < B_BASES; b++)
        C4[((size_t)b * NPAD + n) * 32 + lane] = c[b];
}

// ---------------- fused conv GEMM + bias + LayerNorm + ReLU + residual -----
// Per CTA: D[128 nodes, 128 out] = X[128, 640] @ W^T, X = [C0..C3, h] fp32.
// fp16 2-pass split: X = Xhi + Xlo (both fp16, residual exact to ~2^-24);
// W rounded once to fp16 (error ~2^-12). D = Xhi*W + Xlo*W, fp32 accumulate.
// Then h_new = (l>0 ? h_old : 0) + relu(LN(D + conv_b)), written to g_h.
// Software-pipelined: chunk kc+1's global loads prefetched before kc's MMAs.
__global__ void __launch_bounds__(256, 2)
k_conv_fused(int l, const float* __restrict__ cb,
             const float* __restrict__ lng, const float* __restrict__ lnb,
             int addres) {
    __shared__ __half sXhi[128][40];
    __shared__ __half sXlo[128][40];
    __shared__ __half sW[128][40];
    __shared__ float s_sum[128], s_sq[128];
    __shared__ float s_g[128], s_b[128], s_cb[128];

    int tid  = threadIdx.x;
    int warp = tid >> 5, lane = tid & 31;
    int g = lane >> 2, tig = lane & 3;
    int n0   = blockIdx.x * 128;
    int mrow = (warp >> 1) * 32;
    int ncol = (warp & 1) * 64;

    if (tid < 128) {
        s_sum[tid] = 0.f;
        s_sq[tid]  = 0.f;
        s_g[tid]   = lng[tid];
        s_b[tid]   = lnb[tid];
        s_cb[tid]  = cb[tid];
    }

    uint32_t sXhi_b = (uint32_t)__cvta_generic_to_shared(&sXhi[0][0]);
    uint32_t sXlo_b = (uint32_t)__cvta_generic_to_shared(&sXlo[0][0]);
    uint32_t sW_b   = (uint32_t)__cvta_generic_to_shared(&sW[0][0]);

    // ldmatrix per-lane byte offsets (within the [128][40] fp16 arrays)
    uint32_t a_off = (uint32_t)(((mrow + ((lane >> 3) & 1) * 8 + (lane & 7)) * 40
                                 + (lane >> 4) * 8) * 2);
    uint32_t b_off = (uint32_t)(((ncol + ((lane >> 4) & 1) * 8 + (lane & 7)) * 40
                                 + ((lane >> 3) & 1) * 8) * 2);

    float acc[2][8][4];
#pragma unroll
    for (int mt = 0; mt < 2; mt++)
#pragma unroll
        for (int nt = 0; nt < 8; nt++)
#pragma unroll
            for (int q = 0; q < 4; q++) acc[mt][nt][q] = 0.f;

    const __half* wsrc = g_Wf + (size_t)l * 128 * KTOT;

    int row = tid >> 1, half = tid & 1;

    // prefetch chunk 0
    float4 px[4];
    uint4  pw[2];
    {
        const float4* xs4 = (const float4*)(g_C + ((size_t)0 * NPAD + (n0 + row)) * H
                                            + half * 16);
#pragma unroll
        for (int j = 0; j < 4; j++) px[j] = xs4[j];
        const uint4* w4 = (const uint4*)(wsrc + (size_t)row * KTOT + half * 16);
        pw[0] = w4[0]; pw[1] = w4[1];
    }

    for (int kc = 0; kc < 20; kc++) {
        __syncthreads();   // previous chunk's MMA reads complete
        // store prefetched X (fp16 hi/lo split) and W to smem
#pragma unroll
        for (int j = 0; j < 4; j++) {
            float4 v = px[j];
            float hx = __half2float(__float2half_rn(v.x));
            float hy = __half2float(__float2half_rn(v.y));
            float hz = __half2float(__float2half_rn(v.z));
            float hw = __half2float(__float2half_rn(v.w));
            int col = half * 16 + j * 4;
            *(uint2*)&sXhi[row][col] = make_uint2(pack_f16(v.x, v.y), pack_f16(v.z, v.w));
            *(uint2*)&sXlo[row][col] = make_uint2(pack_f16(v.x - hx, v.y - hy),
                                                  pack_f16(v.z - hz, v.w - hw));
        }
        *(uint4*)&sW[row][half * 16]     = pw[0];
        *(uint4*)&sW[row][half * 16 + 8] = pw[1];
        __syncthreads();

        // prefetch chunk kc+1 (overlaps the MMA section below)
        if (kc < 19) {
            int kn = kc + 1;
            int c = kn >> 2, koff = (kn & 3) * 32;
            const float* xs = (c < 4)
                ? g_C + ((size_t)c * NPAD + (n0 + row)) * H + koff + half * 16
                : g_h + (size_t)(n0 + row) * H + koff + half * 16;
            const float4* xs4 = (const float4*)xs;
#pragma unroll
            for (int j = 0; j < 4; j++) px[j] = xs4[j];
            const uint4* w4 = (const uint4*)(wsrc + (size_t)row * KTOT + kn * 32 + half * 16);
            pw[0] = w4[0]; pw[1] = w4[1];
        }

#pragma unroll
        for (int ks = 0; ks < 32; ks += 16) {
            uint32_t ah[2][4], al[2][4], bb[8][2];
            uint32_t ksb = (uint32_t)(ks * 2);
#pragma unroll
            for (int mt = 0; mt < 2; mt++) {
                uint32_t mo = (uint32_t)(mt * 16 * 40 * 2) + ksb;
                LDSM4(ah[mt][0], ah[mt][1], ah[mt][2], ah[mt][3], sXhi_b + a_off + mo);
                LDSM4(al[mt][0], al[mt][1], al[mt][2], al[mt][3], sXlo_b + a_off + mo);
            }
#pragma unroll
            for (int np = 0; np < 4; np++) {
                uint32_t no = (uint32_t)(np * 16 * 40 * 2) + ksb;
                LDSM4(bb[2 * np][0], bb[2 * np][1], bb[2 * np + 1][0], bb[2 * np + 1][1],
                      sW_b + b_off + no);
            }
#pragma unroll
            for (int mt = 0; mt < 2; mt++)
#pragma unroll
                for (int nt = 0; nt < 8; nt++) {
                    MMAF16(acc[mt][nt], ah[mt], bb[nt]);   // hi pass
                    MMAF16(acc[mt][nt], al[mt], bb[nt]);   // lo pass
                }
        }
    }

    // ---- fused epilogue: bias -> LN stats -> LN+ReLU+residual -> g_h ----
#pragma unroll
    for (int mt = 0; mt < 2; mt++) {
        float s0 = 0.f, q0 = 0.f, s1 = 0.f, q1 = 0.f;
#pragma unroll
        for (int nt = 0; nt < 8; nt++) {
            int colg = ncol + nt * 8 + tig * 2;
            float bx = s_cb[colg], by = s_cb[colg + 1];
            float a0 = acc[mt][nt][0] + bx, a1 = acc[mt][nt][1] + by;
            float a2 = acc[mt][nt][2] + bx, a3 = acc[mt][nt][3] + by;
            acc[mt][nt][0] = a0; acc[mt][nt][1] = a1;
            acc[mt][nt][2] = a2; acc[mt][nt][3] = a3;
            s0 += a0 + a1; q0 += a0 * a0 + a1 * a1;
            s1 += a2 + a3; q1 += a2 * a2 + a3 * a3;
        }
#pragma unroll
        for (int o = 1; o <= 2; o <<= 1) {
            s0 += __shfl_xor_sync(0xFFFFFFFFu, s0, o);
            q0 += __shfl_xor_sync(0xFFFFFFFFu, q0, o);
            s1 += __shfl_xor_sync(0xFFFFFFFFu, s1, o);
            q1 += __shfl_xor_sync(0xFFFFFFFFu, q1, o);
        }
        if (tig == 0) {
            int rl = mrow + mt * 16 + g;
            atomicAdd(&s_sum[rl], s0);
            atomicAdd(&s_sq[rl], q0);
            atomicAdd(&s_sum[rl + 8], s1);
            atomicAdd(&s_sq[rl + 8], q1);
        }
    }
    __syncthreads();

#pragma unroll
    for (int mt = 0; mt < 2; mt++) {
        int rl = mrow + mt * 16 + g;
        float mu0 = s_sum[rl] * (1.0f / 128.0f);
        float v0  = s_sq[rl] * (1.0f / 128.0f) - mu0 * mu0;
        float rs0 = rsqrtf(v0 + 1e-5f);
        float mu1 = s_sum[rl + 8] * (1.0f / 128.0f);
        float v1  = s_sq[rl + 8] * (1.0f / 128.0f) - mu1 * mu1;
        float rs1 = rsqrtf(v1 + 1e-5f);
        float* h0 = g_h + (size_t)(n0 + rl) * H;
        float* h1 = g_h + (size_t)(n0 + rl + 8) * H;
#pragma unroll
        for (int nt = 0; nt < 8; nt++) {
            int colg = ncol + nt * 8 + tig * 2;
            float gx = s_g[colg], gy = s_g[colg + 1];
            float bx = s_b[colg], by = s_b[colg + 1];
            float y0 = fmaxf((acc[mt][nt][0] - mu0) * rs0 * gx + bx, 0.f);
            float y1 = fmaxf((acc[mt][nt][1] - mu0) * rs0 * gy + by, 0.f);
            float y2 = fmaxf((acc[mt][nt][2] - mu1) * rs1 * gx + bx, 0.f);
            float y3 = fmaxf((acc[mt][nt][3] - mu1) * rs1 * gy + by, 0.f);
            if (addres) {
                float2 o0 = *(float2*)(h0 + colg);
                float2 o1 = *(float2*)(h1 + colg);
                y0 += o0.x; y1 += o0.y; y2 += o1.x; y3 += o1.y;
            }
            *(float2*)(h0 + colg) = make_float2(y0, y1);
            *(float2*)(h1 + colg) = make_float2(y2, y3);
        }
    }
}

// ---------------- output head: relu(h @ h1_w + h1_b) @ h2_w + h2_b ---------
__global__ void k_head(const float* __restrict__ w1, const float* __restrict__ b1,
                       const float* __restrict__ w2, const float* __restrict__ b2,
                       float* __restrict__ out) {
    __shared__ float sm[12288];
    int tid = threadIdx.x;
    int n0  = blockIdx.x * 64;
    int ty = tid >> 4, tx = tid & 15;
    float acc[4][8] = {};

    float* Ws = sm;
    float* Xt = sm + 8192;
    float4* Ws4 = (float4*)Ws;
    const float4* Xt4 = (const float4*)Xt;

    for (int s = 0; s < 2; s++) {
        int kb = s * 64;
        __syncthreads();
#pragma unroll
        for (int i = 0; i < 8; i++) {
            int q = i * 256 + tid;
            Ws4[q] = ((const float4*)w1)[kb * 32 + q];
        }
#pragma unroll
        for (int i = 0; i < 4; i++) {
            int q = i * 256 + tid;
            int node = q & 63;
            int kq   = q >> 6;
            float4 v = ((const float4*)g_h)[(size_t)(n0 + node) * 32 + kb / 4 + kq];
            Xt[(kq * 4 + 0) * 64 + node] = v.x;
            Xt[(kq * 4 + 1) * 64 + node] = v.y;
            Xt[(kq * 4 + 2) * 64 + node] = v.z;
            Xt[(kq * 4 + 3) * 64 + node] = v.w;
        }
        __syncthreads();
#pragma unroll 8
        for (int k = 0; k < 64; k++) {
            float4 xa = Xt4[k * 16 + ty];
            float4 wa = Ws4[k * 32 + tx];
            float4 wb = Ws4[k * 32 + 16 + tx];
            float xv[4] = {xa.x, xa.y, xa.z, xa.w};
            float wv[8] = {wa.x, wa.y, wa.z, wa.w, wb.x, wb.y, wb.z, wb.w};
#pragma unroll
            for (int i = 0; i < 4; i++)
#pragma unroll
                for (int j = 0; j < 8; j++) acc[i][j] += xv[i] * wv[j];
        }
    }

    __syncthreads();
    float* Ts  = sm;              // [64][132]
    float* W2t = sm + 64 * 132;   // [8][128]
    float4 b1a = ((const float4*)b1)[tx];
    float4 b1b = ((const float4*)b1)[16 + tx];
#pragma unroll
    for (int i = 0; i < 4; i++) {
        int node = ty * 4 + i;
        float4 t1 = make_float4(fmaxf(acc[i][0] + b1a.x, 0.f), fmaxf(acc[i][1] + b1a.y, 0.f),
                                fmaxf(acc[i][2] + b1a.z, 0.f), fmaxf(acc[i][3] + b1a.w, 0.f));
        float4 t2 = make_float4(fmaxf(acc[i][4] + b1b.x, 0.f), fmaxf(acc[i][5] + b1b.y, 0.f),
                                fmaxf(acc[i][6] + b1b.z, 0.f), fmaxf(acc[i][7] + b1b.w, 0.f));
        ((float4*)(Ts + node * 132))[tx]      = t1;
        ((float4*)(Ts + node * 132))[16 + tx] = t2;
    }
#pragma unroll
    for (int i = 0; i < 4; i++) {
        int idx = i * 256 + tid;
        int k = idx >> 3, o = idx & 7;
        W2t[o * 128 + k] = w2[idx];
    }
    __syncthreads();

#pragma unroll
    for (int p = 0; p < 2; p++) {
        int idx = tid * 2 + p;
        int n = idx >> 3, o = idx & 7;
        int gn = n0 + n;
        float a = 0.f;
        const float4* tr = (const float4*)(Ts + n * 132);
        const float4* wr = (const float4*)(W2t + o * 128);
#pragma unroll
        for (int kq = 0; kq < 32; kq++) {
            float4 t4 = tr[kq];
            float4 w4 = wr[kq];
            a += t4.x * w4.x + t4.y * w4.y + t4.z * w4.z + t4.w * w4.w;
        }
        if (gn < N_NODES) out[(size_t)gn * OUT_DIM + o] = a + b2[o];
    }
}

// ---------------------------------------------------------------------------
// kernel_launch: KERNEL LAUNCHES ONLY (capture-safe; all static smem).
extern "C" void kernel_launch(void* const* d_in, const int* in_sizes, int n_in,
                              void* d_out, int out_size) {
    const float* x      = (const float*)d_in[0];
    const int*   ei     = (const int*)d_in[1];
    const int*   et     = (const int*)d_in[2];
    const float* in_w   = (const float*)d_in[3];
    const float* in_b   = (const float*)d_in[4];
    const float* bases  = (const float*)d_in[5];
    const float* comp   = (const float*)d_in[6];
    const float* root   = (const float*)d_in[7];
    const float* conv_b = (const float*)d_in[8];
    const float* ln_g   = (const float*)d_in[9];
    const float* ln_b   = (const float*)d_in[10];
    const float* h1_w   = (const float*)d_in[11];
    const float* h1_b   = (const float*)d_in[12];
    const float* h2_w   = (const float*)d_in[13];
    const float* h2_b   = (const float*)d_in[14];
    float* out = (float*)d_out;

    // input projection + weight prep
    k_proj<<<NPAD / 64, 256>>>(x, in_w, in_b);
    k_prep<<<(L_LAYERS * KTOT * 128 + 255) / 256, 256>>>(bases, root);

    // CSR build (graph-constant, rebuilt per call; inv folded into scanA)
    k_zero_cnt<<<(NPAD * R_REL + 255) / 256, 256>>>();
    k_count<<<(E_EDGES + 255) / 256, 256>>>(ei, et);
    k_scanA<<<NSCANBLK, 256>>>();
    k_scanB<<<1, 128>>>();
    k_scanC<<<(NPAD + 255) / 256, 256>>>();
    k_fill<<<(E_EDGES + 255) / 256, 256>>>(ei, et);

    for (int l = 0; l < L_LAYERS; l++) {
        k_gather<<<NPAD / 8, 256>>>(comp + (size_t)l * R_REL * B_BASES);
        k_conv_fused<<<NPAD / 128, 256>>>(l, conv_b + (size_t)l * H,
                                          ln_g + (size_t)l * H, ln_b + (size_t)l * H,
                                          l > 0 ? 1 : 0);
    }

    k_head<<<(N_NODES + 63) / 64, 256>>>(h1_w, h1_b, h2_w, h2_b, out);
}